// round 1
// baseline (speedup 1.0000x reference)
#include <cuda_runtime.h>
#include <math.h>

// Problem constants
#define DIMC 1024
#define HC   16
#define DHC  64
#define BC   4
#define LC   4096
#define RC   512
#define SCALEF 0.125f   // 64^-0.5

// ---------------------------------------------------------------------------
// Device-global scratch (allocation-free rule: static __device__ arrays)
// ---------------------------------------------------------------------------
__device__ float g_Q[(size_t)BC * LC * DIMC];   // 64 MB
__device__ float g_K[(size_t)BC * RC * DIMC];   //  8 MB
__device__ float g_V[(size_t)BC * RC * DIMC];   //  8 MB
__device__ float g_O[(size_t)BC * LC * DIMC];   // 64 MB

// ---------------------------------------------------------------------------
// SGEMM: C[M,N] = A[M,K] @ B[K,N], all row-major, fp32.
// 128x128 block tile, BK=16, 8x8 per thread, 256 threads.
// All dims here are multiples of the tile sizes (no bounds checks needed).
// ---------------------------------------------------------------------------
#define GBM 128
#define GBN 128
#define GBK 16
#define GAST 132   // padded smem strides (conflict mitigation)
#define GBST 132

__device__ __forceinline__ void gemm_body(const float* __restrict__ A,
                                          const float* __restrict__ B,
                                          float* __restrict__ C,
                                          int M, int N, int K) {
    __shared__ float As[GBK][GAST];
    __shared__ float Bs[GBK][GBST];
    const int tid = threadIdx.x;
    const float* Ab = A + (size_t)blockIdx.y * GBM * K;
    const float* Bb = B + (size_t)blockIdx.x * GBN;

    float acc[8][8];
#pragma unroll
    for (int i = 0; i < 8; i++)
#pragma unroll
        for (int j = 0; j < 8; j++) acc[i][j] = 0.f;

    const int ty = tid >> 4;   // 0..15
    const int tx = tid & 15;   // 0..15

    for (int k0 = 0; k0 < K; k0 += GBK) {
#pragma unroll
        for (int i = 0; i < 2; i++) {
            int id = tid * 2 + i;          // 0..511
            int ar = id >> 2;              // 0..127
            int ac = (id & 3) * 4;         // 0,4,8,12
            float4 av = *(const float4*)(Ab + (size_t)ar * K + k0 + ac);
            As[ac + 0][ar] = av.x; As[ac + 1][ar] = av.y;
            As[ac + 2][ar] = av.z; As[ac + 3][ar] = av.w;
            int br = id >> 5;              // 0..15
            int bc = (id & 31) * 4;        // 0..124
            *(float4*)&Bs[br][bc] = *(const float4*)(Bb + (size_t)(k0 + br) * N + bc);
        }
        __syncthreads();
#pragma unroll
        for (int k = 0; k < GBK; k++) {
            float a[8], b[8];
            *(float4*)&a[0] = *(float4*)&As[k][ty * 4];
            *(float4*)&a[4] = *(float4*)&As[k][64 + ty * 4];
            *(float4*)&b[0] = *(float4*)&Bs[k][tx * 4];
            *(float4*)&b[4] = *(float4*)&Bs[k][64 + tx * 4];
#pragma unroll
            for (int i = 0; i < 8; i++)
#pragma unroll
                for (int j = 0; j < 8; j++)
                    acc[i][j] = fmaf(a[i], b[j], acc[i][j]);
        }
        __syncthreads();
    }

#pragma unroll
    for (int i = 0; i < 8; i++) {
        int row = blockIdx.y * GBM + ((i < 4) ? (ty * 4 + i) : (64 + ty * 4 + (i - 4)));
        float* Crow = C + (size_t)row * N + (size_t)blockIdx.x * GBN;
        *(float4*)(Crow + tx * 4)      = make_float4(acc[i][0], acc[i][1], acc[i][2], acc[i][3]);
        *(float4*)(Crow + 64 + tx * 4) = make_float4(acc[i][4], acc[i][5], acc[i][6], acc[i][7]);
    }
}

__global__ __launch_bounds__(256) void gemm_q_kernel(const float* __restrict__ x,
                                                     const float* __restrict__ Wq) {
    gemm_body(x, Wq, g_Q, BC * LC, DIMC, DIMC);
}
__global__ __launch_bounds__(256) void gemm_k_kernel(const float* __restrict__ ctx,
                                                     const float* __restrict__ Wk) {
    gemm_body(ctx, Wk, g_K, BC * RC, DIMC, DIMC);
}
__global__ __launch_bounds__(256) void gemm_v_kernel(const float* __restrict__ ctx,
                                                     const float* __restrict__ Wv) {
    gemm_body(ctx, Wv, g_V, BC * RC, DIMC, DIMC);
}
__global__ __launch_bounds__(256) void gemm_o_kernel(const float* __restrict__ Wo,
                                                     float* __restrict__ out) {
    gemm_body(g_O, Wo, out, BC * LC, DIMC, DIMC);
}

// ---------------------------------------------------------------------------
// Attention kernel: one CTA = one (b,h) and a 64-row q tile.
//   S = Q_tile(64x64) @ K_bh^T (64x512)  -> smem
//   softmax rows (512 wide)
//   O = P(64x512) @ V_bh(512x64)
// smem: Ss[64][516] + Qt[64][64] (d-major) + KV[64][64]  = 164,864 B
// ---------------------------------------------------------------------------
#define SSTR 516

__global__ __launch_bounds__(256) void attn_kernel() {
    extern __shared__ float sm[];
    float* Ss = sm;                    // 64 * SSTR
    float* Qt = sm + 64 * SSTR;        // Qt[d*64 + q]
    float* KV = Qt + 64 * 64;          // K chunk: [d*64 + j] ; V chunk: [r*64 + d]

    const int tid = threadIdx.x;
    const int bh = blockIdx.y;
    const int b = bh >> 4;
    const int h = bh & 15;
    const int q0 = blockIdx.x * 64;

    const float* Qg = g_Q + ((size_t)(b * LC + q0)) * DIMC + h * DHC;
    const float* Kg = g_K + ((size_t)(b * RC)) * DIMC + h * DHC;
    const float* Vg = g_V + ((size_t)(b * RC)) * DIMC + h * DHC;

    // Load Q tile transposed: Qt[d][q]
    {
        int r = tid & 63;          // q row
        int c4 = tid >> 6;         // 0..3
#pragma unroll
        for (int p = 0; p < 4; p++) {
            int c = (c4 + p * 4) * 4;
            float4 v = *(const float4*)(Qg + (size_t)r * DIMC + c);
            Qt[(c + 0) * 64 + r] = v.x;
            Qt[(c + 1) * 64 + r] = v.y;
            Qt[(c + 2) * 64 + r] = v.z;
            Qt[(c + 3) * 64 + r] = v.w;
        }
    }

    const int ty = tid >> 4;   // 0..15 -> q rows ty*4..+3
    const int tx = tid & 15;   // 0..15 -> r cols tx*4..+3

    // ---- S = Q @ K^T, in 8 chunks of 64 r-columns ----
    for (int rc = 0; rc < 8; rc++) {
        __syncthreads();
        {   // load K chunk transposed: KV[d][j]
            int r = tid & 63;      // r within chunk
            int c4 = tid >> 6;
#pragma unroll
            for (int p = 0; p < 4; p++) {
                int c = (c4 + p * 4) * 4;
                float4 v = *(const float4*)(Kg + (size_t)(rc * 64 + r) * DIMC + c);
                KV[(c + 0) * 64 + r] = v.x;
                KV[(c + 1) * 64 + r] = v.y;
                KV[(c + 2) * 64 + r] = v.z;
                KV[(c + 3) * 64 + r] = v.w;
            }
        }
        __syncthreads();
        float acc[4][4];
#pragma unroll
        for (int i = 0; i < 4; i++)
#pragma unroll
            for (int j = 0; j < 4; j++) acc[i][j] = 0.f;
#pragma unroll
        for (int d = 0; d < 64; d++) {
            float a[4], bv[4];
            *(float4*)a  = *(float4*)&Qt[d * 64 + ty * 4];
            *(float4*)bv = *(float4*)&KV[d * 64 + tx * 4];
#pragma unroll
            for (int i = 0; i < 4; i++)
#pragma unroll
                for (int j = 0; j < 4; j++)
                    acc[i][j] = fmaf(a[i], bv[j], acc[i][j]);
        }
#pragma unroll
        for (int i = 0; i < 4; i++)
#pragma unroll
            for (int j = 0; j < 4; j++)
                Ss[(ty * 4 + i) * SSTR + rc * 64 + tx * 4 + j] = acc[i][j] * SCALEF;
    }
    __syncthreads();

    // ---- softmax over 512 per row; 8 warps x 8 rows each ----
    {
        const int wid = tid >> 5;
        const int lane = tid & 31;
        for (int r = wid; r < 64; r += 8) {
            float* row = Ss + r * SSTR;
            float m = -1e30f;
            for (int c = lane; c < 512; c += 32) m = fmaxf(m, row[c]);
#pragma unroll
            for (int o = 16; o > 0; o >>= 1) m = fmaxf(m, __shfl_xor_sync(0xffffffffu, m, o));
            float s = 0.f;
            for (int c = lane; c < 512; c += 32) {
                float e = __expf(row[c] - m);
                row[c] = e;
                s += e;
            }
#pragma unroll
            for (int o = 16; o > 0; o >>= 1) s += __shfl_xor_sync(0xffffffffu, s, o);
            float inv = 1.f / s;
            for (int c = lane; c < 512; c += 32) row[c] *= inv;
        }
    }

    // ---- O = P @ V, in 8 chunks of 64 rows of V ----
    float out[4][4];
#pragma unroll
    for (int i = 0; i < 4; i++)
#pragma unroll
        for (int j = 0; j < 4; j++) out[i][j] = 0.f;

    for (int rc = 0; rc < 8; rc++) {
        __syncthreads();
        {   // load V chunk straight: KV[r][d], coalesced
            int r = tid >> 2;      // 0..63
            int c4 = tid & 3;      // 0..3
#pragma unroll
            for (int p = 0; p < 4; p++) {
                int c = (c4 + p * 4) * 4;
                *(float4*)&KV[r * 64 + c] = *(const float4*)(Vg + (size_t)(rc * 64 + r) * DIMC + c);
            }
        }
        __syncthreads();
#pragma unroll 8
        for (int rr = 0; rr < 64; rr++) {
            float a[4], bv[4];
#pragma unroll
            for (int i = 0; i < 4; i++) a[i] = Ss[(ty * 4 + i) * SSTR + rc * 64 + rr];
            *(float4*)bv = *(float4*)&KV[rr * 64 + tx * 4];
#pragma unroll
            for (int i = 0; i < 4; i++)
#pragma unroll
                for (int j = 0; j < 4; j++)
                    out[i][j] = fmaf(a[i], bv[j], out[i][j]);
        }
    }

    // write O tile: row (b, q0+ty*4+i), col h*64 + tx*4 + j
    float* Og = g_O + ((size_t)(b * LC + q0 + ty * 4)) * DIMC + h * DHC + tx * 4;
#pragma unroll
    for (int i = 0; i < 4; i++)
        *(float4*)(Og + (size_t)i * DIMC) = make_float4(out[i][0], out[i][1], out[i][2], out[i][3]);
}

// ---------------------------------------------------------------------------
// Launch
// ---------------------------------------------------------------------------
extern "C" void kernel_launch(void* const* d_in, const int* in_sizes, int n_in,
                              void* d_out, int out_size) {
    const float* x   = (const float*)d_in[0];
    const float* ctx = (const float*)d_in[1];
    const float* Wq  = (const float*)d_in[2];
    const float* Wk  = (const float*)d_in[3];
    const float* Wv  = (const float*)d_in[4];
    const float* Wo  = (const float*)d_in[5];
    float* out = (float*)d_out;

    dim3 blk(256);

    // Projections
    gemm_q_kernel<<<dim3(DIMC / GBN, (BC * LC) / GBM), blk>>>(x, Wq);
    gemm_k_kernel<<<dim3(DIMC / GBN, (BC * RC) / GBM), blk>>>(ctx, Wk);
    gemm_v_kernel<<<dim3(DIMC / GBN, (BC * RC) / GBM), blk>>>(ctx, Wv);

    // Attention
    const int attn_smem = (64 * SSTR + 64 * 64 + 64 * 64) * (int)sizeof(float);  // 164,864 B
    cudaFuncSetAttribute(attn_kernel, cudaFuncAttributeMaxDynamicSharedMemorySize, attn_smem);
    attn_kernel<<<dim3(LC / 64, BC * HC), blk, attn_smem>>>();

    // Output projection
    gemm_o_kernel<<<dim3(DIMC / GBN, (BC * LC) / GBM), blk>>>(Wo, out);
}

// round 3
// speedup vs baseline: 1.5834x; 1.5834x over previous
#include <cuda_runtime.h>
#include <cstdint>
#include <math.h>

// Problem constants
#define DIMC 1024
#define HC   16
#define DHC  64
#define BC   4
#define LC   4096
#define RC   512
#define SCALEF 0.125f   // 64^-0.5

// ---------------------------------------------------------------------------
// Device-global scratch
// ---------------------------------------------------------------------------
__device__ float g_Q [(size_t)BC * LC * DIMC];   // 64 MB
__device__ float g_K [(size_t)BC * RC * DIMC];   //  8 MB
__device__ float g_V [(size_t)BC * RC * DIMC];   //  8 MB
__device__ float g_O [(size_t)BC * LC * DIMC];   // 64 MB (attn out, tf32-rounded)
__device__ float g_Xr[(size_t)BC * LC * DIMC];   // 64 MB (x rounded to tf32)
__device__ float g_Cr[(size_t)BC * RC * DIMC];   //  8 MB (context rounded)
__device__ float g_WqT[(size_t)DIMC * DIMC];     //  4 MB each: W^T, tf32-rounded
__device__ float g_WkT[(size_t)DIMC * DIMC];
__device__ float g_WvT[(size_t)DIMC * DIMC];
__device__ float g_WoT[(size_t)DIMC * DIMC];

// ---------------------------------------------------------------------------
// Helpers
// ---------------------------------------------------------------------------
__device__ __forceinline__ uint32_t smem_u32(const void* p) {
    uint32_t a;
    asm("{ .reg .u64 t; cvta.to.shared.u64 t, %1; cvt.u32.u64 %0, t; }" : "=r"(a) : "l"(p));
    return a;
}
__device__ __forceinline__ float tf32_rn(float x) {
    float y;
    asm("cvt.rna.tf32.f32 %0, %1;" : "=f"(y) : "f"(x));
    return y;
}

#define CP_ASYNC16(dst, src) \
    asm volatile("cp.async.cg.shared.global [%0], [%1], 16;" :: "r"(dst), "l"(src) : "memory")
#define CP_COMMIT() asm volatile("cp.async.commit_group;" ::: "memory")
#define CP_WAIT(n)  asm volatile("cp.async.wait_group %0;" :: "n"(n) : "memory")

__device__ __forceinline__ void mma_tf32(float* c, const uint32_t* a, const uint32_t* b) {
    asm volatile(
        "mma.sync.aligned.m16n8k8.row.col.f32.tf32.tf32.f32 "
        "{%0,%1,%2,%3}, {%4,%5,%6,%7}, {%8,%9}, {%0,%1,%2,%3};"
        : "+f"(c[0]), "+f"(c[1]), "+f"(c[2]), "+f"(c[3])
        : "r"(a[0]), "r"(a[1]), "r"(a[2]), "r"(a[3]), "r"(b[0]), "r"(b[1]));
}

// ---------------------------------------------------------------------------
// Preprocessing kernels (round to tf32; transpose weights)
// ---------------------------------------------------------------------------
__global__ __launch_bounds__(256) void round_copy_kernel(const float* __restrict__ src,
                                                         float* __restrict__ dst, int n4) {
    int i = blockIdx.x * 256 + threadIdx.x;
    if (i < n4) {
        float4 v = ((const float4*)src)[i];
        v.x = tf32_rn(v.x); v.y = tf32_rn(v.y); v.z = tf32_rn(v.z); v.w = tf32_rn(v.w);
        ((float4*)dst)[i] = v;
    }
}

__global__ __launch_bounds__(256) void transpose_round_kernel(const float* __restrict__ W,
                                                              float* __restrict__ Wt) {
    __shared__ float t[32][33];
    int x = blockIdx.x * 32 + threadIdx.x;
#pragma unroll
    for (int i = threadIdx.y; i < 32; i += 8) {
        int y = blockIdx.y * 32 + i;
        t[i][threadIdx.x] = tf32_rn(W[(size_t)y * DIMC + x]);
    }
    __syncthreads();
    int xo = blockIdx.y * 32 + threadIdx.x;
#pragma unroll
    for (int i = threadIdx.y; i < 32; i += 8) {
        int yo = blockIdx.x * 32 + i;
        Wt[(size_t)yo * DIMC + xo] = t[threadIdx.x][i];
    }
}

// ---------------------------------------------------------------------------
// tf32 mma.sync GEMM: C[M,1024] = A[M,1024] @ Bt[N=1024,K=1024]^T
// A, Bt both K-major fp32 (pre-rounded to tf32).
// CTA tile 128x128, BK=16, 3-stage cp.async, 256 threads,
// 8 warps (4 M x 2 N), warp tile 32x64 = 2x8 m16n8k8 tiles.
// ---------------------------------------------------------------------------
#define BK 16
#define SK 20                       // padded smem stride (floats) - conflict-free
#define STG_FLOATS (128 * SK)       // one As or Bs tile
#define STG_STRIDE (2 * STG_FLOATS) // As + Bs per stage
#define GSM_TOTAL (3 * STG_STRIDE * 4)  // 61440 B

__device__ __forceinline__ void load_stage(uint32_t sbase, const float* __restrict__ Ab,
                                           const float* __restrict__ Bb, int kt, int tid) {
    uint32_t sA = sbase;
    uint32_t sB = sbase + STG_FLOATS * 4;
    const float* As_ = Ab + kt * BK;
    const float* Bs_ = Bb + kt * BK;
#pragma unroll
    for (int i = 0; i < 2; i++) {
        int id = tid + i * 256;        // 0..511
        int r = id >> 2;               // 0..127
        int c = id & 3;                // 16B granule
        CP_ASYNC16(sA + (uint32_t)(r * SK * 4 + c * 16), As_ + (size_t)r * DIMC + c * 4);
        CP_ASYNC16(sB + (uint32_t)(r * SK * 4 + c * 16), Bs_ + (size_t)r * DIMC + c * 4);
    }
}

__global__ __launch_bounds__(256) void mma_gemm_kernel(const float* __restrict__ A,
                                                       const float* __restrict__ Bt,
                                                       float* __restrict__ C) {
    extern __shared__ float sm[];
    const int tid = threadIdx.x;
    const int lane = tid & 31;
    const int g = lane >> 2;           // 0..7
    const int tg = lane & 3;           // 0..3
    const int wid = tid >> 5;
    const int wm = (wid & 3) * 32;     // warp M offset
    const int wn = (wid >> 2) * 64;    // warp N offset

    const float* Ab = A  + (size_t)blockIdx.y * 128 * DIMC;
    const float* Bb = Bt + (size_t)blockIdx.x * 128 * DIMC;
    uint32_t sb = smem_u32(sm);

    float acc[2][8][4];
#pragma unroll
    for (int mi = 0; mi < 2; mi++)
#pragma unroll
        for (int nj = 0; nj < 8; nj++)
#pragma unroll
            for (int q = 0; q < 4; q++) acc[mi][nj][q] = 0.f;

    load_stage(sb + 0 * STG_STRIDE * 4, Ab, Bb, 0, tid); CP_COMMIT();
    load_stage(sb + 1 * STG_STRIDE * 4, Ab, Bb, 1, tid); CP_COMMIT();

    const int NKT = DIMC / BK;   // 64
    for (int kt = 0; kt < NKT; kt++) {
        if (kt < NKT - 1) { CP_WAIT(1); } else { CP_WAIT(0); }
        __syncthreads();

        const float* St = sm + (kt % 3) * STG_STRIDE;
        const float* As_ = St + wm * SK;
        const float* Bs_ = St + STG_FLOATS + wn * SK;

#pragma unroll
        for (int kk = 0; kk < BK; kk += 8) {
            uint32_t a[2][4], b[8][2];
#pragma unroll
            for (int mi = 0; mi < 2; mi++) {
                int r0 = mi * 16 + g;
                a[mi][0] = __float_as_uint(As_[r0 * SK + kk + tg]);
                a[mi][1] = __float_as_uint(As_[(r0 + 8) * SK + kk + tg]);
                a[mi][2] = __float_as_uint(As_[r0 * SK + kk + tg + 4]);
                a[mi][3] = __float_as_uint(As_[(r0 + 8) * SK + kk + tg + 4]);
            }
#pragma unroll
            for (int nj = 0; nj < 8; nj++) {
                int c0 = nj * 8 + g;
                b[nj][0] = __float_as_uint(Bs_[c0 * SK + kk + tg]);
                b[nj][1] = __float_as_uint(Bs_[c0 * SK + kk + tg + 4]);
            }
#pragma unroll
            for (int mi = 0; mi < 2; mi++)
#pragma unroll
                for (int nj = 0; nj < 8; nj++)
                    mma_tf32(acc[mi][nj], a[mi], b[nj]);
        }

        if (kt + 2 < NKT) {
            load_stage(sb + ((kt + 2) % 3) * STG_STRIDE * 4, Ab, Bb, kt + 2, tid);
            CP_COMMIT();
        }
    }

    // epilogue: c0,c1 at (row, 2*tg), c2,c3 at (row+8, 2*tg)
    size_t rowb = (size_t)blockIdx.y * 128 + wm + g;
    size_t colb = (size_t)blockIdx.x * 128 + wn;
#pragma unroll
    for (int mi = 0; mi < 2; mi++) {
        float* C0 = C + (rowb + mi * 16) * DIMC + colb;
        float* C1 = C0 + 8 * DIMC;
#pragma unroll
        for (int nj = 0; nj < 8; nj++) {
            *(float2*)(C0 + nj * 8 + tg * 2) = make_float2(acc[mi][nj][0], acc[mi][nj][1]);
            *(float2*)(C1 + nj * 8 + tg * 2) = make_float2(acc[mi][nj][2], acc[mi][nj][3]);
        }
    }
}

// ---------------------------------------------------------------------------
// Attention kernel (FFMA, fp32): one CTA = (b,h) x 64-row q tile.
// Output rounded to tf32 (feeds the tf32 O-projection).
// ---------------------------------------------------------------------------
#define SSTR 516

__global__ __launch_bounds__(256) void attn_kernel() {
    extern __shared__ float sm[];
    float* Ss = sm;                    // 64 * SSTR
    float* Qt = sm + 64 * SSTR;        // Qt[d*64 + q]
    float* KV = Qt + 64 * 64;          // chunk buffer

    const int tid = threadIdx.x;
    const int bh = blockIdx.y;
    const int b = bh >> 4;
    const int h = bh & 15;
    const int q0 = blockIdx.x * 64;

    const float* Qg = g_Q + ((size_t)(b * LC + q0)) * DIMC + h * DHC;
    const float* Kg = g_K + ((size_t)(b * RC)) * DIMC + h * DHC;
    const float* Vg = g_V + ((size_t)(b * RC)) * DIMC + h * DHC;

    {
        int r = tid & 63;
        int c4 = tid >> 6;
#pragma unroll
        for (int p = 0; p < 4; p++) {
            int c = (c4 + p * 4) * 4;
            float4 v = *(const float4*)(Qg + (size_t)r * DIMC + c);
            Qt[(c + 0) * 64 + r] = v.x;
            Qt[(c + 1) * 64 + r] = v.y;
            Qt[(c + 2) * 64 + r] = v.z;
            Qt[(c + 3) * 64 + r] = v.w;
        }
    }

    const int ty = tid >> 4;
    const int tx = tid & 15;

    for (int rc = 0; rc < 8; rc++) {
        __syncthreads();
        {
            int r = tid & 63;
            int c4 = tid >> 6;
#pragma unroll
            for (int p = 0; p < 4; p++) {
                int c = (c4 + p * 4) * 4;
                float4 v = *(const float4*)(Kg + (size_t)(rc * 64 + r) * DIMC + c);
                KV[(c + 0) * 64 + r] = v.x;
                KV[(c + 1) * 64 + r] = v.y;
                KV[(c + 2) * 64 + r] = v.z;
                KV[(c + 3) * 64 + r] = v.w;
            }
        }
        __syncthreads();
        float acc[4][4];
#pragma unroll
        for (int i = 0; i < 4; i++)
#pragma unroll
            for (int j = 0; j < 4; j++) acc[i][j] = 0.f;
#pragma unroll
        for (int d = 0; d < 64; d++) {
            float a[4], bv[4];
            *(float4*)a  = *(float4*)&Qt[d * 64 + ty * 4];
            *(float4*)bv = *(float4*)&KV[d * 64 + tx * 4];
#pragma unroll
            for (int i = 0; i < 4; i++)
#pragma unroll
                for (int j = 0; j < 4; j++)
                    acc[i][j] = fmaf(a[i], bv[j], acc[i][j]);
        }
#pragma unroll
        for (int i = 0; i < 4; i++)
#pragma unroll
            for (int j = 0; j < 4; j++)
                Ss[(ty * 4 + i) * SSTR + rc * 64 + tx * 4 + j] = acc[i][j] * SCALEF;
    }
    __syncthreads();

    {
        const int wid = tid >> 5;
        const int lane = tid & 31;
        for (int r = wid; r < 64; r += 8) {
            float* row = Ss + r * SSTR;
            float m = -1e30f;
            for (int c = lane; c < 512; c += 32) m = fmaxf(m, row[c]);
#pragma unroll
            for (int o = 16; o > 0; o >>= 1) m = fmaxf(m, __shfl_xor_sync(0xffffffffu, m, o));
            float s = 0.f;
            for (int c = lane; c < 512; c += 32) {
                float e = __expf(row[c] - m);
                row[c] = e;
                s += e;
            }
#pragma unroll
            for (int o = 16; o > 0; o >>= 1) s += __shfl_xor_sync(0xffffffffu, s, o);
            float inv = 1.f / s;
            for (int c = lane; c < 512; c += 32) row[c] *= inv;
        }
    }

    float out[4][4];
#pragma unroll
    for (int i = 0; i < 4; i++)
#pragma unroll
        for (int j = 0; j < 4; j++) out[i][j] = 0.f;

    for (int rc = 0; rc < 8; rc++) {
        __syncthreads();
        {
            int r = tid >> 2;
            int c4 = tid & 3;
#pragma unroll
            for (int p = 0; p < 4; p++) {
                int c = (c4 + p * 4) * 4;
                *(float4*)&KV[r * 64 + c] = *(const float4*)(Vg + (size_t)(rc * 64 + r) * DIMC + c);
            }
        }
        __syncthreads();
#pragma unroll 8
        for (int rr = 0; rr < 64; rr++) {
            float a[4], bv[4];
#pragma unroll
            for (int i = 0; i < 4; i++) a[i] = Ss[(ty * 4 + i) * SSTR + rc * 64 + rr];
            *(float4*)bv = *(float4*)&KV[rr * 64 + tx * 4];
#pragma unroll
            for (int i = 0; i < 4; i++)
#pragma unroll
                for (int j = 0; j < 4; j++)
                    out[i][j] = fmaf(a[i], bv[j], out[i][j]);
        }
    }

    float* Og = g_O + ((size_t)(b * LC + q0 + ty * 4)) * DIMC + h * DHC + tx * 4;
#pragma unroll
    for (int i = 0; i < 4; i++)
        *(float4*)(Og + (size_t)i * DIMC) =
            make_float4(tf32_rn(out[i][0]), tf32_rn(out[i][1]),
                        tf32_rn(out[i][2]), tf32_rn(out[i][3]));
}

// ---------------------------------------------------------------------------
// Launch
// ---------------------------------------------------------------------------
extern "C" void kernel_launch(void* const* d_in, const int* in_sizes, int n_in,
                              void* d_out, int out_size) {
    const float* x   = (const float*)d_in[0];
    const float* ctx = (const float*)d_in[1];
    const float* Wq  = (const float*)d_in[2];
    const float* Wk  = (const float*)d_in[3];
    const float* Wv  = (const float*)d_in[4];
    const float* Wo  = (const float*)d_in[5];
    float* out = (float*)d_out;

    void *pXr, *pCr, *pWqT, *pWkT, *pWvT, *pWoT, *pQ, *pK, *pV, *pO;
    cudaGetSymbolAddress(&pXr, g_Xr);
    cudaGetSymbolAddress(&pCr, g_Cr);
    cudaGetSymbolAddress(&pWqT, g_WqT);
    cudaGetSymbolAddress(&pWkT, g_WkT);
    cudaGetSymbolAddress(&pWvT, g_WvT);
    cudaGetSymbolAddress(&pWoT, g_WoT);
    cudaGetSymbolAddress(&pQ, g_Q);
    cudaGetSymbolAddress(&pK, g_K);
    cudaGetSymbolAddress(&pV, g_V);
    cudaGetSymbolAddress(&pO, g_O);

    cudaFuncSetAttribute(mma_gemm_kernel, cudaFuncAttributeMaxDynamicSharedMemorySize, GSM_TOTAL);
    const int attn_smem = (64 * SSTR + 64 * 64 + 64 * 64) * (int)sizeof(float);
    cudaFuncSetAttribute(attn_kernel, cudaFuncAttributeMaxDynamicSharedMemorySize, attn_smem);

    // Preprocess: round activations, transpose+round weights
    round_copy_kernel<<<(BC * LC * DIMC / 4 + 255) / 256, 256>>>(x,   (float*)pXr, BC * LC * DIMC / 4);
    round_copy_kernel<<<(BC * RC * DIMC / 4 + 255) / 256, 256>>>(ctx, (float*)pCr, BC * RC * DIMC / 4);
    dim3 tb(32, 8), tg(DIMC / 32, DIMC / 32);
    transpose_round_kernel<<<tg, tb>>>(Wq, (float*)pWqT);
    transpose_round_kernel<<<tg, tb>>>(Wk, (float*)pWkT);
    transpose_round_kernel<<<tg, tb>>>(Wv, (float*)pWvT);
    transpose_round_kernel<<<tg, tb>>>(Wo, (float*)pWoT);

    // Projections (tf32 tensor cores via mma.sync)
    mma_gemm_kernel<<<dim3(DIMC / 128, (BC * LC) / 128), 256, GSM_TOTAL>>>((const float*)pXr, (const float*)pWqT, (float*)pQ);
    mma_gemm_kernel<<<dim3(DIMC / 128, (BC * RC) / 128), 256, GSM_TOTAL>>>((const float*)pCr, (const float*)pWkT, (float*)pK);
    mma_gemm_kernel<<<dim3(DIMC / 128, (BC * RC) / 128), 256, GSM_TOTAL>>>((const float*)pCr, (const float*)pWvT, (float*)pV);

    // Attention (fp32 FFMA)
    attn_kernel<<<dim3(LC / 64, BC * HC), 256, attn_smem>>>();

    // Output projection (tf32 tensor cores via mma.sync)
    mma_gemm_kernel<<<dim3(DIMC / 128, (BC * LC) / 128), 256, GSM_TOTAL>>>((const float*)pO, (const float*)pWoT, out);
}

// round 6
// speedup vs baseline: 2.5094x; 1.5848x over previous
#include <cuda_runtime.h>
#include <cstdint>
#include <math.h>

// Problem constants
#define DIMC 1024
#define HC   16
#define DHC  64
#define BC   4
#define LC   4096
#define RC   512
#define SCALEF 0.125f   // 64^-0.5

// ---------------------------------------------------------------------------
// Device-global scratch
// ---------------------------------------------------------------------------
__device__ float g_Q [(size_t)BC * LC * DIMC];   // 64 MB (tf32-rounded, pre-scaled)
__device__ float g_K [(size_t)BC * RC * DIMC];   //  8 MB (tf32-rounded)
__device__ float g_V [(size_t)BC * RC * DIMC];   //  8 MB (tf32-rounded)
__device__ float g_O [(size_t)BC * LC * DIMC];   // 64 MB (attn out, tf32-rounded)
__device__ float g_Xr[(size_t)BC * LC * DIMC];   // 64 MB (x rounded to tf32)
__device__ float g_Cr[(size_t)BC * RC * DIMC];   //  8 MB (context rounded)
__device__ float g_WqT[(size_t)DIMC * DIMC];     //  4 MB each: W^T, tf32-rounded
__device__ float g_WkT[(size_t)DIMC * DIMC];
__device__ float g_WvT[(size_t)DIMC * DIMC];
__device__ float g_WoT[(size_t)DIMC * DIMC];

// ---------------------------------------------------------------------------
// Helpers
// ---------------------------------------------------------------------------
__device__ __forceinline__ uint32_t smem_u32(const void* p) {
    uint32_t a;
    asm("{ .reg .u64 t; cvta.to.shared.u64 t, %1; cvt.u32.u64 %0, t; }" : "=r"(a) : "l"(p));
    return a;
}
__device__ __forceinline__ float tf32_rn(float x) {
    float y;
    asm("cvt.rna.tf32.f32 %0, %1;" : "=f"(y) : "f"(x));
    return y;
}

#define CP_ASYNC16(dst, src) \
    asm volatile("cp.async.cg.shared.global [%0], [%1], 16;" :: "r"(dst), "l"(src) : "memory")
#define CP_COMMIT() asm volatile("cp.async.commit_group;" ::: "memory")
#define CP_WAIT(n)  asm volatile("cp.async.wait_group %0;" :: "n"(n) : "memory")

__device__ __forceinline__ void mma_tf32(float* c, const uint32_t* a, const uint32_t* b) {
    asm volatile(
        "mma.sync.aligned.m16n8k8.row.col.f32.tf32.tf32.f32 "
        "{%0,%1,%2,%3}, {%4,%5,%6,%7}, {%8,%9}, {%0,%1,%2,%3};"
        : "+f"(c[0]), "+f"(c[1]), "+f"(c[2]), "+f"(c[3])
        : "r"(a[0]), "r"(a[1]), "r"(a[2]), "r"(a[3]), "r"(b[0]), "r"(b[1]));
}

// ---------------------------------------------------------------------------
// Preprocessing kernels (round to tf32; transpose weights)
// ---------------------------------------------------------------------------
__global__ __launch_bounds__(256) void round_copy_kernel(const float* __restrict__ src,
                                                         float* __restrict__ dst, int n4) {
    int i = blockIdx.x * 256 + threadIdx.x;
    if (i < n4) {
        float4 v = ((const float4*)src)[i];
        v.x = tf32_rn(v.x); v.y = tf32_rn(v.y); v.z = tf32_rn(v.z); v.w = tf32_rn(v.w);
        ((float4*)dst)[i] = v;
    }
}

__global__ __launch_bounds__(256) void transpose_round_kernel(const float* __restrict__ W,
                                                              float* __restrict__ Wt,
                                                              float scale) {
    __shared__ float t[32][33];
    int x = blockIdx.x * 32 + threadIdx.x;
#pragma unroll
    for (int i = threadIdx.y; i < 32; i += 8) {
        int y = blockIdx.y * 32 + i;
        t[i][threadIdx.x] = tf32_rn(W[(size_t)y * DIMC + x] * scale);
    }
    __syncthreads();
    int xo = blockIdx.y * 32 + threadIdx.x;
#pragma unroll
    for (int i = threadIdx.y; i < 32; i += 8) {
        int yo = blockIdx.x * 32 + i;
        Wt[(size_t)yo * DIMC + xo] = t[threadIdx.x][i];
    }
}

// ---------------------------------------------------------------------------
// tf32 mma.sync GEMM: C[M,1024] = A[M,1024] @ Bt[N=1024,K=1024]^T
// round_out=1 -> write tf32-rounded C (for Q/K/V feeding attention mma).
// ---------------------------------------------------------------------------
#define BK 16
#define SK 20
#define STG_FLOATS (128 * SK)
#define STG_STRIDE (2 * STG_FLOATS)
#define GSM_TOTAL (3 * STG_STRIDE * 4)  // 61440 B

__device__ __forceinline__ void load_stage(uint32_t sbase, const float* __restrict__ Ab,
                                           const float* __restrict__ Bb, int kt, int tid) {
    uint32_t sA = sbase;
    uint32_t sB = sbase + STG_FLOATS * 4;
    const float* As_ = Ab + kt * BK;
    const float* Bs_ = Bb + kt * BK;
#pragma unroll
    for (int i = 0; i < 2; i++) {
        int id = tid + i * 256;
        int r = id >> 2;
        int c = id & 3;
        CP_ASYNC16(sA + (uint32_t)(r * SK * 4 + c * 16), As_ + (size_t)r * DIMC + c * 4);
        CP_ASYNC16(sB + (uint32_t)(r * SK * 4 + c * 16), Bs_ + (size_t)r * DIMC + c * 4);
    }
}

__global__ __launch_bounds__(256) void mma_gemm_kernel(const float* __restrict__ A,
                                                       const float* __restrict__ Bt,
                                                       float* __restrict__ C,
                                                       int round_out) {
    extern __shared__ float sm[];
    const int tid = threadIdx.x;
    const int lane = tid & 31;
    const int g = lane >> 2;
    const int tg = lane & 3;
    const int wid = tid >> 5;
    const int wm = (wid & 3) * 32;
    const int wn = (wid >> 2) * 64;

    const float* Ab = A  + (size_t)blockIdx.y * 128 * DIMC;
    const float* Bb = Bt + (size_t)blockIdx.x * 128 * DIMC;
    uint32_t sb = smem_u32(sm);

    float acc[2][8][4];
#pragma unroll
    for (int mi = 0; mi < 2; mi++)
#pragma unroll
        for (int nj = 0; nj < 8; nj++)
#pragma unroll
            for (int q = 0; q < 4; q++) acc[mi][nj][q] = 0.f;

    load_stage(sb + 0 * STG_STRIDE * 4, Ab, Bb, 0, tid); CP_COMMIT();
    load_stage(sb + 1 * STG_STRIDE * 4, Ab, Bb, 1, tid); CP_COMMIT();

    const int NKT = DIMC / BK;
    for (int kt = 0; kt < NKT; kt++) {
        if (kt < NKT - 1) { CP_WAIT(1); } else { CP_WAIT(0); }
        __syncthreads();

        const float* St = sm + (kt % 3) * STG_STRIDE;
        const float* As_ = St + wm * SK;
        const float* Bs_ = St + STG_FLOATS + wn * SK;

#pragma unroll
        for (int kk = 0; kk < BK; kk += 8) {
            uint32_t a[2][4], b[8][2];
#pragma unroll
            for (int mi = 0; mi < 2; mi++) {
                int r0 = mi * 16 + g;
                a[mi][0] = __float_as_uint(As_[r0 * SK + kk + tg]);
                a[mi][1] = __float_as_uint(As_[(r0 + 8) * SK + kk + tg]);
                a[mi][2] = __float_as_uint(As_[r0 * SK + kk + tg + 4]);
                a[mi][3] = __float_as_uint(As_[(r0 + 8) * SK + kk + tg + 4]);
            }
#pragma unroll
            for (int nj = 0; nj < 8; nj++) {
                int c0 = nj * 8 + g;
                b[nj][0] = __float_as_uint(Bs_[c0 * SK + kk + tg]);
                b[nj][1] = __float_as_uint(Bs_[c0 * SK + kk + tg + 4]);
            }
#pragma unroll
            for (int mi = 0; mi < 2; mi++)
#pragma unroll
                for (int nj = 0; nj < 8; nj++)
                    mma_tf32(acc[mi][nj], a[mi], b[nj]);
        }

        if (kt + 2 < NKT) {
            load_stage(sb + ((kt + 2) % 3) * STG_STRIDE * 4, Ab, Bb, kt + 2, tid);
            CP_COMMIT();
        }
    }

    if (round_out) {
#pragma unroll
        for (int mi = 0; mi < 2; mi++)
#pragma unroll
            for (int nj = 0; nj < 8; nj++)
#pragma unroll
                for (int q = 0; q < 4; q++) acc[mi][nj][q] = tf32_rn(acc[mi][nj][q]);
    }

    size_t rowb = (size_t)blockIdx.y * 128 + wm + g;
    size_t colb = (size_t)blockIdx.x * 128 + wn;
#pragma unroll
    for (int mi = 0; mi < 2; mi++) {
        float* C0 = C + (rowb + mi * 16) * DIMC + colb;
        float* C1 = C0 + 8 * DIMC;
#pragma unroll
        for (int nj = 0; nj < 8; nj++) {
            *(float2*)(C0 + nj * 8 + tg * 2) = make_float2(acc[mi][nj][0], acc[mi][nj][1]);
            *(float2*)(C1 + nj * 8 + tg * 2) = make_float2(acc[mi][nj][2], acc[mi][nj][3]);
        }
    }
}

// ---------------------------------------------------------------------------
// Tensor-core attention: one CTA = (b,h) x 64 q rows.
//   S(64x512) = Qs(64x64,pre-scaled) @ K^T   (tf32 mma, 4 chunks of 128, cp.async db)
//   softmax: 2 passes, unnormalized exp stored tf32, inv-sum deferred
//   O(64x64) = P(64x512) @ V                 (tf32 mma, V transposed in smem)
// smem floats: Ss 64*516 | Qs 64*68 | KB 2*128*68 (Vt 64*132 aliases) | inv 64
// ---------------------------------------------------------------------------
#define SSTR 516
#define QSTR 68
#define KSTR 68
#define VSTR 132
#define S_OFF   0
#define Q_OFF   33024
#define KB_OFF  37376
#define INV_OFF 54784
#define ATTN_SMEM ((INV_OFF + 64) * 4)   // 219,392 B

__global__ __launch_bounds__(256) void attn_mma_kernel() {
    extern __shared__ float sm[];
    float* Ss = sm + S_OFF;
    float* Qs = sm + Q_OFF;
    float* KB = sm + KB_OFF;
    float* sInv = sm + INV_OFF;
    uint32_t sb = smem_u32(sm);
    const uint32_t qb = sb + Q_OFF * 4;
    const uint32_t kb = sb + KB_OFF * 4;

    const int tid = threadIdx.x;
    const int lane = tid & 31;
    const int g = lane >> 2;
    const int tg = lane & 3;
    const int wid = tid >> 5;
    const int bh = blockIdx.y;
    const int b = bh >> 4;
    const int h = bh & 15;
    const int q0 = blockIdx.x * 64;

    const float* Qg = g_Q + ((size_t)(b * LC + q0)) * DIMC + h * DHC;
    const float* Kg = g_K + ((size_t)(b * RC)) * DIMC + h * DHC;
    const float* Vg = g_V + ((size_t)(b * RC)) * DIMC + h * DHC;

    // async prologue: Q tile (64x64) + K chunk 0 (128x64)
#pragma unroll
    for (int i = 0; i < 4; i++) {
        int id = tid + i * 256;
        int r = id >> 4, c = id & 15;
        CP_ASYNC16(qb + (uint32_t)((r * QSTR + c * 4) * 4), Qg + (size_t)r * DIMC + c * 4);
    }
#pragma unroll
    for (int i = 0; i < 8; i++) {
        int id = tid + i * 256;            // 0..2047
        int r = id >> 4, c = id & 15;      // 128 rows x 16 granules
        CP_ASYNC16(kb + (uint32_t)((r * KSTR + c * 4) * 4), Kg + (size_t)r * DIMC + c * 4);
    }
    CP_COMMIT();

    // ---- S phase: 8 warps as 2m x 4n (32x32 warp tiles) ----
    const int wmS = (wid & 1) * 32;
    const int wnS = (wid >> 1) * 32;
    for (int rc = 0; rc < 4; rc++) {
        CP_WAIT(0);
        __syncthreads();
        if (rc + 1 < 4) {
            uint32_t dstb = kb + (uint32_t)(((rc + 1) & 1) * 8704 * 4);
            const float* src = Kg + (size_t)(rc + 1) * 128 * DIMC;
#pragma unroll
            for (int i = 0; i < 8; i++) {
                int id = tid + i * 256;
                int r = id >> 4, c = id & 15;
                CP_ASYNC16(dstb + (uint32_t)((r * KSTR + c * 4) * 4), src + (size_t)r * DIMC + c * 4);
            }
            CP_COMMIT();
        }
        const float* Ksm = KB + (rc & 1) * 8704;
        float acc[2][4][4];
#pragma unroll
        for (int mi = 0; mi < 2; mi++)
#pragma unroll
            for (int nj = 0; nj < 4; nj++)
#pragma unroll
                for (int q = 0; q < 4; q++) acc[mi][nj][q] = 0.f;

#pragma unroll
        for (int kk = 0; kk < 64; kk += 8) {
            uint32_t a[2][4], bb[4][2];
#pragma unroll
            for (int mi = 0; mi < 2; mi++) {
                int r0 = wmS + mi * 16 + g;
                a[mi][0] = __float_as_uint(Qs[r0 * QSTR + kk + tg]);
                a[mi][1] = __float_as_uint(Qs[(r0 + 8) * QSTR + kk + tg]);
                a[mi][2] = __float_as_uint(Qs[r0 * QSTR + kk + tg + 4]);
                a[mi][3] = __float_as_uint(Qs[(r0 + 8) * QSTR + kk + tg + 4]);
            }
#pragma unroll
            for (int nj = 0; nj < 4; nj++) {
                int c0 = wnS + nj * 8 + g;
                bb[nj][0] = __float_as_uint(Ksm[c0 * KSTR + kk + tg]);
                bb[nj][1] = __float_as_uint(Ksm[c0 * KSTR + kk + tg + 4]);
            }
#pragma unroll
            for (int mi = 0; mi < 2; mi++)
#pragma unroll
                for (int nj = 0; nj < 4; nj++)
                    mma_tf32(acc[mi][nj], a[mi], bb[nj]);
        }
#pragma unroll
        for (int mi = 0; mi < 2; mi++) {
            int row = wmS + mi * 16 + g;
#pragma unroll
            for (int nj = 0; nj < 4; nj++) {
                int col = rc * 128 + wnS + nj * 8 + tg * 2;
                *(float2*)&Ss[row * SSTR + col]       = make_float2(acc[mi][nj][0], acc[mi][nj][1]);
                *(float2*)&Ss[(row + 8) * SSTR + col] = make_float2(acc[mi][nj][2], acc[mi][nj][3]);
            }
        }
    }
    __syncthreads();

    // ---- softmax: 2 passes; store unnormalized tf32 exp; keep 1/sum ----
    for (int r = wid; r < 64; r += 8) {
        float* row = Ss + r * SSTR;
        float m = -1e30f;
        for (int c = lane; c < 512; c += 32) m = fmaxf(m, row[c]);
#pragma unroll
        for (int o = 16; o > 0; o >>= 1) m = fmaxf(m, __shfl_xor_sync(0xffffffffu, m, o));
        float s = 0.f;
        for (int c = lane; c < 512; c += 32) {
            float e = tf32_rn(__expf(row[c] - m));
            row[c] = e;
            s += e;
        }
#pragma unroll
        for (int o = 16; o > 0; o >>= 1) s += __shfl_xor_sync(0xffffffffu, s, o);
        if (lane == 0) sInv[r] = 1.f / s;
    }

    // ---- PV phase: 8 warps as 4m x 2n (16x32 warp tiles) ----
    const int wmP = (wid & 3) * 16;
    const int wnP = (wid >> 2) * 32;
    float po[4][4];
#pragma unroll
    for (int nj = 0; nj < 4; nj++)
#pragma unroll
        for (int q = 0; q < 4; q++) po[nj][q] = 0.f;

    for (int rc = 0; rc < 4; rc++) {
        __syncthreads();   // prior reads of KB/Vt done (or softmax done at rc=0)
        // load V chunk transposed: Vt[d][r]
#pragma unroll
        for (int i = 0; i < 8; i++) {
            int id = tid + i * 256;
            int r = id & 127;
            int c = (id >> 7) * 4;
            float4 v = *(const float4*)(Vg + (size_t)(rc * 128 + r) * DIMC + c);
            KB[(c + 0) * VSTR + r] = v.x;
            KB[(c + 1) * VSTR + r] = v.y;
            KB[(c + 2) * VSTR + r] = v.z;
            KB[(c + 3) * VSTR + r] = v.w;
        }
        __syncthreads();
#pragma unroll
        for (int kk = 0; kk < 128; kk += 8) {
            uint32_t a[4], bb[4][2];
            int r0 = wmP + g;
            int colk = rc * 128 + kk + tg;
            a[0] = __float_as_uint(Ss[r0 * SSTR + colk]);
            a[1] = __float_as_uint(Ss[(r0 + 8) * SSTR + colk]);
            a[2] = __float_as_uint(Ss[r0 * SSTR + colk + 4]);
            a[3] = __float_as_uint(Ss[(r0 + 8) * SSTR + colk + 4]);
#pragma unroll
            for (int nj = 0; nj < 4; nj++) {
                int c0 = wnP + nj * 8 + g;
                bb[nj][0] = __float_as_uint(KB[c0 * VSTR + kk + tg]);
                bb[nj][1] = __float_as_uint(KB[c0 * VSTR + kk + tg + 4]);
            }
#pragma unroll
            for (int nj = 0; nj < 4; nj++)
                mma_tf32(po[nj], a, bb[nj]);
        }
    }

    // ---- epilogue: normalize (fp32), round to tf32, store to g_O ----
    float inv0 = sInv[wmP + g];
    float inv1 = sInv[wmP + g + 8];
    float* Og = g_O + ((size_t)(b * LC + q0 + wmP + g)) * DIMC + h * DHC + wnP;
#pragma unroll
    for (int nj = 0; nj < 4; nj++) {
        int col = nj * 8 + tg * 2;
        *(float2*)(Og + col) =
            make_float2(tf32_rn(po[nj][0] * inv0), tf32_rn(po[nj][1] * inv0));
        *(float2*)(Og + 8 * DIMC + col) =
            make_float2(tf32_rn(po[nj][2] * inv1), tf32_rn(po[nj][3] * inv1));
    }
}

// ---------------------------------------------------------------------------
// Launch
// ---------------------------------------------------------------------------
extern "C" void kernel_launch(void* const* d_in, const int* in_sizes, int n_in,
                              void* d_out, int out_size) {
    const float* x   = (const float*)d_in[0];
    const float* ctx = (const float*)d_in[1];
    const float* Wq  = (const float*)d_in[2];
    const float* Wk  = (const float*)d_in[3];
    const float* Wv  = (const float*)d_in[4];
    const float* Wo  = (const float*)d_in[5];
    float* out = (float*)d_out;

    void *pXr, *pCr, *pWqT, *pWkT, *pWvT, *pWoT, *pQ, *pK, *pV, *pO;
    cudaGetSymbolAddress(&pXr, g_Xr);
    cudaGetSymbolAddress(&pCr, g_Cr);
    cudaGetSymbolAddress(&pWqT, g_WqT);
    cudaGetSymbolAddress(&pWkT, g_WkT);
    cudaGetSymbolAddress(&pWvT, g_WvT);
    cudaGetSymbolAddress(&pWoT, g_WoT);
    cudaGetSymbolAddress(&pQ, g_Q);
    cudaGetSymbolAddress(&pK, g_K);
    cudaGetSymbolAddress(&pV, g_V);
    cudaGetSymbolAddress(&pO, g_O);

    cudaFuncSetAttribute(mma_gemm_kernel, cudaFuncAttributeMaxDynamicSharedMemorySize, GSM_TOTAL);
    cudaFuncSetAttribute(attn_mma_kernel, cudaFuncAttributeMaxDynamicSharedMemorySize, ATTN_SMEM);

    // Preprocess: round activations, transpose+round weights (Wq pre-scaled)
    round_copy_kernel<<<(BC * LC * DIMC / 4 + 255) / 256, 256>>>(x,   (float*)pXr, BC * LC * DIMC / 4);
    round_copy_kernel<<<(BC * RC * DIMC / 4 + 255) / 256, 256>>>(ctx, (float*)pCr, BC * RC * DIMC / 4);
    dim3 tb(32, 8), tg(DIMC / 32, DIMC / 32);
    transpose_round_kernel<<<tg, tb>>>(Wq, (float*)pWqT, SCALEF);
    transpose_round_kernel<<<tg, tb>>>(Wk, (float*)pWkT, 1.0f);
    transpose_round_kernel<<<tg, tb>>>(Wv, (float*)pWvT, 1.0f);
    transpose_round_kernel<<<tg, tb>>>(Wo, (float*)pWoT, 1.0f);

    // Projections (tf32 mma.sync), outputs rounded to tf32 for attention
    mma_gemm_kernel<<<dim3(DIMC / 128, (BC * LC) / 128), 256, GSM_TOTAL>>>((const float*)pXr, (const float*)pWqT, (float*)pQ, 1);
    mma_gemm_kernel<<<dim3(DIMC / 128, (BC * RC) / 128), 256, GSM_TOTAL>>>((const float*)pCr, (const float*)pWkT, (float*)pK, 1);
    mma_gemm_kernel<<<dim3(DIMC / 128, (BC * RC) / 128), 256, GSM_TOTAL>>>((const float*)pCr, (const float*)pWvT, (float*)pV, 1);

    // Attention (tf32 mma.sync)
    attn_mma_kernel<<<dim3(LC / 64, BC * HC), 256, ATTN_SMEM>>>();

    // Output projection (full-precision fp32 store)
    mma_gemm_kernel<<<dim3(DIMC / 128, (BC * LC) / 128), 256, GSM_TOTAL>>>((const float*)pO, (const float*)pWoT, out, 0);
}